// round 1
// baseline (speedup 1.0000x reference)
#include <cuda_runtime.h>
#include <cuda_bf16.h>

// TDNN = implicit GEMM:
//   out[b, n, t] = relu(bias[n] + sum_{k<5, i<512} x[b, t+k, i] * w[n, i, k])
// Dimensions: B=32, T=1024, T_out=1020, D_in=512, D_out=512, KW=5, K=2560.
//
// Strategy (round 1, fp32 SIMT baseline):
//  - Pre-transpose weights once per launch into W2[k][i][n] (coalesced in n)
//    held in a __device__ scratch buffer (no allocation).
//  - Classic 128x128 block tile, 8x8 per thread, BK=16, smem-staged.
//  - Block tile: rows = D_out slice (from W2, coalesced float4 loads, no
//    transpose needed), cols = t slice (x loaded float4 along i, scattered
//    into smem transposed). Output stores are coalesced along t.

#define DIN   512
#define DOUT  512
#define TIN   1024
#define TOUT  1020
#define KW    5
#define KTOT  (DIN * KW)   // 2560

__device__ float g_w2[KW * DIN * DOUT];   // [k][i][n], 5.24 MB scratch

__global__ void transform_weights(const float* __restrict__ w) {
    int idx = blockIdx.x * blockDim.x + threadIdx.x;   // idx = (k*DIN + i)*DOUT + n
    if (idx >= KW * DIN * DOUT) return;
    int n = idx & (DOUT - 1);
    int i = (idx >> 9) & (DIN - 1);
    int k = idx >> 18;
    g_w2[idx] = w[n * (DIN * KW) + i * KW + k];
}

// 256 threads: tx (0..15) -> t direction, ty (0..15) -> n direction.
__global__ __launch_bounds__(256, 2)
void tdnn_gemm(const float* __restrict__ x,
               const float* __restrict__ bias,
               float* __restrict__ out) {
    __shared__ float As[16][128];   // weights  [kk][n]
    __shared__ float Bs[16][132];   // x        [kk][t]  (+4 pad vs store conflicts)

    const int b  = blockIdx.z;
    const int t0 = blockIdx.y * 128;
    const int n0 = blockIdx.x * 128;
    const int tid = threadIdx.x;
    const int tx = tid & 15;    // t
    const int ty = tid >> 4;    // n

    const float* xb = x + (size_t)b * TIN * DIN;

    float acc[8][8];
    #pragma unroll
    for (int i2 = 0; i2 < 8; ++i2)
        #pragma unroll
        for (int j = 0; j < 8; ++j) acc[i2][j] = 0.0f;

    for (int kc = 0; kc < KTOT; kc += 16) {
        const int k  = kc >> 9;        // conv tap (constant within the 16-chunk)
        const int ib = kc & (DIN - 1); // input-channel base

        // ---- load weight tile: 16 kk x 128 n, coalesced float4 ----
        #pragma unroll
        for (int it = 0; it < 2; ++it) {
            int idx = tid + it * 256;           // 0..511
            int kkl = idx >> 5;                 // 0..15
            int nn4 = (idx & 31) << 2;          // 0..124 step 4
            float4 v = *(const float4*)&g_w2[(size_t)(kc + kkl) * DOUT + n0 + nn4];
            *(float4*)&As[kkl][nn4] = v;
        }
        // ---- load x tile: 16 kk x 128 t; float4 along i, scatter-transposed ----
        #pragma unroll
        for (int it = 0; it < 2; ++it) {
            int idx = tid + it * 256;           // 0..511
            int tt  = idx >> 2;                 // 0..127
            int kkl = (idx & 3) << 2;           // 0,4,8,12
            int row = t0 + tt + k;              // time index into x
            float4 v = make_float4(0.f, 0.f, 0.f, 0.f);
            if (row < TIN)
                v = *(const float4*)&xb[(size_t)row * DIN + ib + kkl];
            Bs[kkl + 0][tt] = v.x;
            Bs[kkl + 1][tt] = v.y;
            Bs[kkl + 2][tt] = v.z;
            Bs[kkl + 3][tt] = v.w;
        }
        __syncthreads();

        #pragma unroll
        for (int kk = 0; kk < 16; ++kk) {
            float a[8], bb[8];
            *(float4*)&a[0]  = *(float4*)&As[kk][ty * 8];
            *(float4*)&a[4]  = *(float4*)&As[kk][ty * 8 + 4];
            *(float4*)&bb[0] = *(float4*)&Bs[kk][tx * 8];
            *(float4*)&bb[4] = *(float4*)&Bs[kk][tx * 8 + 4];
            #pragma unroll
            for (int i2 = 0; i2 < 8; ++i2)
                #pragma unroll
                for (int j = 0; j < 8; ++j)
                    acc[i2][j] = fmaf(a[i2], bb[j], acc[i2][j]);
        }
        __syncthreads();
    }

    // ---- epilogue: bias + relu, coalesced stores along t ----
    #pragma unroll
    for (int i2 = 0; i2 < 8; ++i2) {
        const int n = n0 + ty * 8 + i2;
        const float bv = bias[n];
        float* orow = out + ((size_t)b * DOUT + n) * TOUT;
        const int tbase = t0 + tx * 8;
        if (tbase + 7 < TOUT) {
            float4 v0, v1;
            v0.x = fmaxf(acc[i2][0] + bv, 0.f);
            v0.y = fmaxf(acc[i2][1] + bv, 0.f);
            v0.z = fmaxf(acc[i2][2] + bv, 0.f);
            v0.w = fmaxf(acc[i2][3] + bv, 0.f);
            v1.x = fmaxf(acc[i2][4] + bv, 0.f);
            v1.y = fmaxf(acc[i2][5] + bv, 0.f);
            v1.z = fmaxf(acc[i2][6] + bv, 0.f);
            v1.w = fmaxf(acc[i2][7] + bv, 0.f);
            *(float4*)&orow[tbase]     = v0;   // 1020 % 4 == 0 -> 16B aligned
            *(float4*)&orow[tbase + 4] = v1;
        } else {
            #pragma unroll
            for (int j = 0; j < 8; ++j) {
                int t = tbase + j;
                if (t < TOUT) orow[t] = fmaxf(acc[i2][j] + bv, 0.f);
            }
        }
    }
}

extern "C" void kernel_launch(void* const* d_in, const int* in_sizes, int n_in,
                              void* d_out, int out_size) {
    const float* x    = (const float*)d_in[0];   // [B, T, D_in]
    const float* w    = (const float*)d_in[1];   // [D_out, D_in, KW]
    const float* bias = (const float*)d_in[2];   // [D_out]
    float* out = (float*)d_out;                  // [B, D_out, T_out]

    const int wtotal = KW * DIN * DOUT;
    transform_weights<<<(wtotal + 255) / 256, 256>>>(w);

    dim3 grid(DOUT / 128, (TOUT + 127) / 128, 32);  // (4, 8, 32)
    tdnn_gemm<<<grid, 256>>>(x, bias, out);
}

// round 3
// speedup vs baseline: 2.8738x; 2.8738x over previous
#include <cuda_runtime.h>
#include <cuda_bf16.h>
#include <cstdint>

// TDNN as implicit GEMM with warp-level bf16 mma.sync (portable PTX -> HMMA),
// fp32 emulated via 3-term bf16 split: C = Ah*Bh + Al*Bh + Ah*Bl.
//   out[b,n,t] = relu(bias[n] + sum_{kappa<2560} W2[n][kappa] * x[b, t*512+kappa])
// W2[n][k*512+i] = w[n][i][k]; the x window per (b,t) is contiguous memory.

#define DIN   512
#define DOUT  512
#define TIN   1024
#define TOUT  1020
#define KW    5
#define KTOT  2560
#define BATCH 32

#define TILE_M 128        // Dout per CTA
#define TILE_N 256        // t per CTA
#define KC     64         // bf16 K per stage (128B rows, SW128)
#define NSTAGE (KTOT / KC)

// ---------------- scratch (no allocation allowed) ----------------
__device__ __nv_bfloat16 g_xh[(size_t)BATCH * TIN * DIN];
__device__ __nv_bfloat16 g_xl[(size_t)BATCH * TIN * DIN];
__device__ __nv_bfloat16 g_wh[DOUT * KTOT];   // [n][k*512+i]
__device__ __nv_bfloat16 g_wl[DOUT * KTOT];

__global__ void split_x_kernel(const float* __restrict__ x) {
    int i = blockIdx.x * 256 + threadIdx.x;
    float v = x[i];
    __nv_bfloat16 h = __float2bfloat16(v);
    g_xh[i] = h;
    g_xl[i] = __float2bfloat16(v - __bfloat162float(h));
}

__global__ void split_w_kernel(const float* __restrict__ w) {
    int idx = blockIdx.x * 256 + threadIdx.x;
    if (idx >= DOUT * KTOT) return;
    int n   = idx / KTOT;
    int rem = idx - n * KTOT;
    int k   = rem >> 9;
    int i   = rem & 511;
    float v = w[(n * DIN + i) * KW + k];
    __nv_bfloat16 h = __float2bfloat16(v);
    g_wh[idx] = h;
    g_wl[idx] = __float2bfloat16(v - __bfloat162float(h));
}

// ---------------- PTX helpers (portable, no sm_103a-only ops) -------------
__device__ __forceinline__ uint32_t smem_u32(const void* p) {
    uint32_t a;
    asm("{ .reg .u64 t; cvta.to.shared.u64 t, %1; cvt.u32.u64 %0, t; }"
        : "=r"(a) : "l"(p));
    return a;
}
__device__ __forceinline__ void cpa16(uint32_t dst, const void* src) {
    asm volatile("cp.async.cg.shared.global [%0], [%1], 16;"
                 :: "r"(dst), "l"(__cvta_generic_to_global(src)) : "memory");
}
__device__ __forceinline__ void ldsm4(uint32_t* r, uint32_t a) {
    asm volatile("ldmatrix.sync.aligned.m8n8.x4.shared.b16 {%0,%1,%2,%3}, [%4];"
                 : "=r"(r[0]), "=r"(r[1]), "=r"(r[2]), "=r"(r[3]) : "r"(a));
}
__device__ __forceinline__ void mma16816(float* c, const uint32_t* a,
                                         const uint32_t* b) {
    asm volatile(
        "mma.sync.aligned.m16n8k16.row.col.f32.bf16.bf16.f32 "
        "{%0,%1,%2,%3}, {%4,%5,%6,%7}, {%8,%9}, {%0,%1,%2,%3};"
        : "+f"(c[0]), "+f"(c[1]), "+f"(c[2]), "+f"(c[3])
        : "r"(a[0]), "r"(a[1]), "r"(a[2]), "r"(a[3]), "r"(b[0]), "r"(b[1]));
}

// SMEM stage: Ah +0 (16KB) Al +16384 Bh +32768 (32KB) Bl +65536 -> 96KB
#define AH_OFF 0u
#define AL_OFF 16384u
#define BH_OFF 32768u
#define BL_OFF 65536u
#define STAGE_BYTES 98304u
#define SMEM_BYTES (1024 + 2 * 98304)

extern __shared__ char dyn_smem[];

__global__ __launch_bounds__(512, 1)
void tdnn_mma(const float* __restrict__ bias, float* __restrict__ out) {
    const int tid  = threadIdx.x;
    const int wid  = tid >> 5;
    const int lane = tid & 31;
    const int d0 = blockIdx.x * TILE_M;   // Dout tile base
    const int t0 = blockIdx.y * TILE_N;   // time tile base
    const int b  = blockIdx.z;

    const int wm = wid & 1;   // 2 warps along M (64 rows each)
    const int wn = wid >> 1;  // 8 warps along N (32 cols each)

    const uint32_t sb = (smem_u32(dyn_smem) + 1023u) & ~1023u;

    // ---- per-lane ldmatrix address precompute (SW128: 128B rows) ----
    const int grp  = lane >> 3;          // which 8x8 matrix this lane addresses
    const int apar = grp >> 1;           // A: k-chunk parity (0: k0-7, 1: k8-15)
    uint32_t a_off[4]; int a_sw[4];
    #pragma unroll
    for (int mt = 0; mt < 4; ++mt) {
        int r = wm * 64 + mt * 16 + ((grp & 1) << 3) + (lane & 7);
        a_off[mt] = (uint32_t)(r << 7);
        a_sw[mt]  = r & 7;
    }
    const int bpar  = grp & 1;           // B: k-chunk parity
    const int ntoff = grp >> 1;          // which n8-tile within the pair
    uint32_t b_off[2]; int b_sw[2];
    #pragma unroll
    for (int np = 0; np < 2; ++np) {
        int r = wn * 32 + np * 16 + ntoff * 8 + (lane & 7);
        b_off[np] = (uint32_t)(r << 7);
        b_sw[np]  = r & 7;
    }

    float acc[4][4][4];
    #pragma unroll
    for (int mt = 0; mt < 4; ++mt)
        #pragma unroll
        for (int nt = 0; nt < 4; ++nt)
            #pragma unroll
            for (int q = 0; q < 4; ++q) acc[mt][nt][q] = 0.0f;

    // ---- stage loader: cp.async into SW128-swizzled tiles ----
    auto load_stage = [&](int s) {
        const int kc = s * KC;
        const uint32_t base = sb + (uint32_t)(s & 1) * STAGE_BYTES;
        #pragma unroll 2
        for (int c = tid; c < 1024; c += 512) {      // A: 128 rows x 8 chunks
            int row = c >> 3, ch = c & 7;
            uint32_t off = (uint32_t)((row << 7) | (((ch ^ (row & 7)) << 4)));
            size_t gi = (size_t)(d0 + row) * KTOT + kc + ch * 8;
            cpa16(base + AH_OFF + off, g_wh + gi);
            cpa16(base + AL_OFF + off, g_wl + gi);
        }
        #pragma unroll 4
        for (int c = tid; c < 2048; c += 512) {      // B: 256 rows x 8 chunks
            int row = c >> 3, ch = c & 7;
            int t = t0 + row;
            if (t > TIN - KW) t = TIN - KW;          // clamp; outputs masked
            uint32_t off = (uint32_t)((row << 7) | (((ch ^ (row & 7)) << 4)));
            size_t gi = (size_t)b * (TIN * DIN) + (size_t)t * DIN + kc + ch * 8;
            cpa16(base + BH_OFF + off, g_xh + gi);
            cpa16(base + BL_OFF + off, g_xl + gi);
        }
        asm volatile("cp.async.commit_group;" ::: "memory");
    };

    load_stage(0);
    load_stage(1);

    for (int s = 0; s < NSTAGE; ++s) {
        if (s < NSTAGE - 2) asm volatile("cp.async.wait_group 1;" ::: "memory");
        else                asm volatile("cp.async.wait_group 0;" ::: "memory");
        __syncthreads();

        const uint32_t base = sb + (uint32_t)(s & 1) * STAGE_BYTES;
        #pragma unroll
        for (int kk = 0; kk < 4; ++kk) {
            uint32_t ah[4][4], al[4][4], bh[8], bl[8];
            #pragma unroll
            for (int mt = 0; mt < 4; ++mt) {
                uint32_t co = (uint32_t)((((kk << 1) + apar) ^ a_sw[mt]) << 4);
                ldsm4(ah[mt], base + AH_OFF + a_off[mt] + co);
                ldsm4(al[mt], base + AL_OFF + a_off[mt] + co);
            }
            #pragma unroll
            for (int np = 0; np < 2; ++np) {
                uint32_t co = (uint32_t)((((kk << 1) + bpar) ^ b_sw[np]) << 4);
                ldsm4(&bh[np * 4], base + BH_OFF + b_off[np] + co);
                ldsm4(&bl[np * 4], base + BL_OFF + b_off[np] + co);
            }
            #pragma unroll
            for (int mt = 0; mt < 4; ++mt)
                #pragma unroll
                for (int nt = 0; nt < 4; ++nt)
                    mma16816(acc[mt][nt], ah[mt], &bh[nt * 2]);
            #pragma unroll
            for (int mt = 0; mt < 4; ++mt)
                #pragma unroll
                for (int nt = 0; nt < 4; ++nt)
                    mma16816(acc[mt][nt], al[mt], &bh[nt * 2]);
            #pragma unroll
            for (int mt = 0; mt < 4; ++mt)
                #pragma unroll
                for (int nt = 0; nt < 4; ++nt)
                    mma16816(acc[mt][nt], ah[mt], &bl[nt * 2]);
        }
        __syncthreads();
        if (s + 2 < NSTAGE) load_stage(s + 2);
    }

    // ---- epilogue: bias + relu; float2 stores (t even, TOUT even) ----
    const int quad = lane >> 2;
    const int qt   = (lane & 3) << 1;
    #pragma unroll
    for (int mt = 0; mt < 4; ++mt) {
        const int m = d0 + wm * 64 + mt * 16 + quad;
        const float bv0 = bias[m];
        const float bv1 = bias[m + 8];
        float* r0 = out + ((size_t)b * DOUT + m) * TOUT;
        float* r1 = r0 + 8 * TOUT;
        #pragma unroll
        for (int nt = 0; nt < 4; ++nt) {
            const int t = t0 + wn * 32 + nt * 8 + qt;
            if (t < TOUT) {
                float2 v0, v1;
                v0.x = fmaxf(acc[mt][nt][0] + bv0, 0.0f);
                v0.y = fmaxf(acc[mt][nt][1] + bv0, 0.0f);
                v1.x = fmaxf(acc[mt][nt][2] + bv1, 0.0f);
                v1.y = fmaxf(acc[mt][nt][3] + bv1, 0.0f);
                *(float2*)&r0[t] = v0;
                *(float2*)&r1[t] = v1;
            }
        }
    }
}

extern "C" void kernel_launch(void* const* d_in, const int* in_sizes, int n_in,
                              void* d_out, int out_size) {
    const float* x    = (const float*)d_in[0];   // [B, T, D_in]
    const float* w    = (const float*)d_in[1];   // [D_out, D_in, KW]
    const float* bias = (const float*)d_in[2];   // [D_out]
    float* out = (float*)d_out;                  // [B, D_out, T_out]

    cudaFuncSetAttribute(tdnn_mma, cudaFuncAttributeMaxDynamicSharedMemorySize,
                         SMEM_BYTES);

    split_x_kernel<<<(BATCH * TIN * DIN) / 256, 256>>>(x);
    split_w_kernel<<<(DOUT * KTOT + 255) / 256, 256>>>(w);

    dim3 grid(DOUT / TILE_M, (TOUT + TILE_N - 1) / TILE_N, BATCH);  // (4,4,32)
    tdnn_mma<<<grid, 512, SMEM_BYTES>>>(bias, out);
}

// round 4
// speedup vs baseline: 4.3496x; 1.5135x over previous
#include <cuda_runtime.h>
#include <cuda_fp16.h>
#include <cstdint>

// TDNN as implicit GEMM with warp-level fp16 mma.sync (portable PTX -> HMMA).
// Asymmetric precision: weights split exactly into fp16 hi+lo, x in single
// fp16 -> C = Wh*X + Wl*X (2 MMA passes). Error dominated by fp16 rounding of
// x: ~3e-4 << 1e-3.
//   out[b,n,t] = relu(bias[n] + sum_{kappa<2560} W2[n][kappa] * x[b, t*512+kappa])
// W2[n][k*512+i] = w[n][i][k]; the x window per (b,t) is contiguous memory.

#define DIN   512
#define DOUT  512
#define TIN   1024
#define TOUT  1020
#define KW    5
#define KTOT  2560
#define BATCH 32

#define TILE_M 128        // Dout per CTA
#define TILE_N 256        // t per CTA
#define KC     64         // fp16 K per stage (128B rows, SW128)
#define NSTAGE (KTOT / KC)

#define XVEC_THREADS ((BATCH * TIN * DIN) / 4)        // 4 elems per thread
#define XVEC_BLOCKS  (XVEC_THREADS / 256)             // 16384
#define W_BLOCKS     ((DOUT * KTOT + 255) / 256)      // 5120

// ---------------- scratch (no allocation allowed) ----------------
__device__ __half g_xh[(size_t)BATCH * TIN * DIN];
__device__ __half g_wh[DOUT * KTOT];   // [n][k*512+i]
__device__ __half g_wl[DOUT * KTOT];

// Fused split kernel (keeps launch count at 2 per call).
__global__ void split_inputs(const float* __restrict__ x,
                             const float* __restrict__ w) {
    int bid = blockIdx.x;
    if (bid < XVEC_BLOCKS) {
        int gid = bid * 256 + threadIdx.x;
        int i4 = gid * 4;
        float4 v = *(const float4*)(x + i4);
        __half2 h0 = __floats2half2_rn(v.x, v.y);
        __half2 h1 = __floats2half2_rn(v.z, v.w);
        uint2 pk;
        pk.x = *(uint32_t*)&h0;
        pk.y = *(uint32_t*)&h1;
        *(uint2*)(g_xh + i4) = pk;
    } else {
        int idx = (bid - XVEC_BLOCKS) * 256 + threadIdx.x;
        if (idx >= DOUT * KTOT) return;
        int n   = idx / KTOT;
        int rem = idx - n * KTOT;
        int k   = rem >> 9;
        int i   = rem & 511;
        float v = w[(n * DIN + i) * KW + k];
        __half h = __float2half_rn(v);
        g_wh[idx] = h;
        g_wl[idx] = __float2half_rn(v - __half2float(h));
    }
}

// ---------------- PTX helpers (portable, no sm_103a-only ops) -------------
__device__ __forceinline__ uint32_t smem_u32(const void* p) {
    uint32_t a;
    asm("{ .reg .u64 t; cvta.to.shared.u64 t, %1; cvt.u32.u64 %0, t; }"
        : "=r"(a) : "l"(p));
    return a;
}
__device__ __forceinline__ void cpa16(uint32_t dst, const void* src) {
    asm volatile("cp.async.cg.shared.global [%0], [%1], 16;"
                 :: "r"(dst), "l"(__cvta_generic_to_global(src)) : "memory");
}
__device__ __forceinline__ void ldsm4(uint32_t* r, uint32_t a) {
    asm volatile("ldmatrix.sync.aligned.m8n8.x4.shared.b16 {%0,%1,%2,%3}, [%4];"
                 : "=r"(r[0]), "=r"(r[1]), "=r"(r[2]), "=r"(r[3]) : "r"(a));
}
__device__ __forceinline__ void mma16816(float* c, const uint32_t* a,
                                         const uint32_t* b) {
    asm volatile(
        "mma.sync.aligned.m16n8k16.row.col.f32.f16.f16.f32 "
        "{%0,%1,%2,%3}, {%4,%5,%6,%7}, {%8,%9}, {%0,%1,%2,%3};"
        : "+f"(c[0]), "+f"(c[1]), "+f"(c[2]), "+f"(c[3])
        : "r"(a[0]), "r"(a[1]), "r"(a[2]), "r"(a[3]), "r"(b[0]), "r"(b[1]));
}

// SMEM stage: Ah +0 (16KB)  Al +16384 (16KB)  B +32768 (32KB) -> 64KB/stage
#define AH_OFF 0u
#define AL_OFF 16384u
#define B_OFF  32768u
#define STAGE_BYTES 65536u
#define NBUF 3
#define SMEM_BYTES (1024 + NBUF * 65536)

extern __shared__ char dyn_smem[];

__global__ __launch_bounds__(512, 1)
void tdnn_mma(const float* __restrict__ bias, float* __restrict__ out) {
    const int tid  = threadIdx.x;
    const int wid  = tid >> 5;
    const int lane = tid & 31;
    const int d0 = blockIdx.x * TILE_M;   // Dout tile base
    const int t0 = blockIdx.y * TILE_N;   // time tile base
    const int b  = blockIdx.z;

    const int wm = wid & 1;   // 2 warps along M (64 rows each)
    const int wn = wid >> 1;  // 8 warps along N (32 cols each)

    const uint32_t sb = (smem_u32(dyn_smem) + 1023u) & ~1023u;

    // ---- per-lane ldmatrix address precompute (SW128: 128B rows) ----
    const int grp  = lane >> 3;
    const int apar = grp >> 1;           // A: k-chunk parity
    uint32_t a_off[4]; int a_sw[4];
    #pragma unroll
    for (int mt = 0; mt < 4; ++mt) {
        int r = wm * 64 + mt * 16 + ((grp & 1) << 3) + (lane & 7);
        a_off[mt] = (uint32_t)(r << 7);
        a_sw[mt]  = r & 7;
    }
    const int bpar  = grp & 1;           // B: k-chunk parity
    const int ntoff = grp >> 1;
    uint32_t b_off[2]; int b_sw[2];
    #pragma unroll
    for (int np = 0; np < 2; ++np) {
        int r = wn * 32 + np * 16 + ntoff * 8 + (lane & 7);
        b_off[np] = (uint32_t)(r << 7);
        b_sw[np]  = r & 7;
    }

    float acc[4][4][4];
    #pragma unroll
    for (int mt = 0; mt < 4; ++mt)
        #pragma unroll
        for (int nt = 0; nt < 4; ++nt)
            #pragma unroll
            for (int q = 0; q < 4; ++q) acc[mt][nt][q] = 0.0f;

    // ---- stage loader ----
    auto load_stage = [&](int s, uint32_t base) {
        const int kc = s * KC;
        #pragma unroll 2
        for (int c = tid; c < 1024; c += 512) {      // A: 128 rows x 8 chunks
            int row = c >> 3, ch = c & 7;
            uint32_t off = (uint32_t)((row << 7) | ((ch ^ (row & 7)) << 4));
            size_t gi = (size_t)(d0 + row) * KTOT + kc + ch * 8;
            cpa16(base + AH_OFF + off, g_wh + gi);
            cpa16(base + AL_OFF + off, g_wl + gi);
        }
        #pragma unroll 4
        for (int c = tid; c < 2048; c += 512) {      // B: 256 rows x 8 chunks
            int row = c >> 3, ch = c & 7;
            int t = t0 + row;
            if (t > TIN - KW) t = TIN - KW;          // clamp; outputs masked
            uint32_t off = (uint32_t)((row << 7) | ((ch ^ (row & 7)) << 4));
            size_t gi = (size_t)b * (TIN * DIN) + (size_t)t * DIN + kc + ch * 8;
            cpa16(base + B_OFF + off, g_xh + gi);
        }
        asm volatile("cp.async.commit_group;" ::: "memory");
    };

    load_stage(0, sb);
    load_stage(1, sb + STAGE_BYTES);
    load_stage(2, sb + 2 * STAGE_BYTES);

    int cbuf = 0, lbuf = 0;   // compute / load buffer indices (mod 3)
    for (int s = 0; s < NSTAGE; ++s) {
        if (s <= NSTAGE - 3)      asm volatile("cp.async.wait_group 2;" ::: "memory");
        else if (s == NSTAGE - 2) asm volatile("cp.async.wait_group 1;" ::: "memory");
        else                      asm volatile("cp.async.wait_group 0;" ::: "memory");
        __syncthreads();

        const uint32_t base = sb + (uint32_t)cbuf * STAGE_BYTES;
        #pragma unroll
        for (int kk = 0; kk < 4; ++kk) {
            uint32_t ah[4][4], al[4][4], bf[8];
            #pragma unroll
            for (int mt = 0; mt < 4; ++mt) {
                uint32_t co = (uint32_t)((((kk << 1) + apar) ^ a_sw[mt]) << 4);
                ldsm4(ah[mt], base + AH_OFF + a_off[mt] + co);
                ldsm4(al[mt], base + AL_OFF + a_off[mt] + co);
            }
            #pragma unroll
            for (int np = 0; np < 2; ++np) {
                uint32_t co = (uint32_t)((((kk << 1) + bpar) ^ b_sw[np]) << 4);
                ldsm4(&bf[np * 4], base + B_OFF + b_off[np] + co);
            }
            #pragma unroll
            for (int mt = 0; mt < 4; ++mt)
                #pragma unroll
                for (int nt = 0; nt < 4; ++nt)
                    mma16816(acc[mt][nt], ah[mt], &bf[nt * 2]);
            #pragma unroll
            for (int mt = 0; mt < 4; ++mt)
                #pragma unroll
                for (int nt = 0; nt < 4; ++nt)
                    mma16816(acc[mt][nt], al[mt], &bf[nt * 2]);
        }
        __syncthreads();
        if (s + 3 < NSTAGE) load_stage(s + 3, sb + (uint32_t)lbuf * STAGE_BYTES);
        cbuf = (cbuf == NBUF - 1) ? 0 : cbuf + 1;
        lbuf = (lbuf == NBUF - 1) ? 0 : lbuf + 1;
    }

    // ---- epilogue: bias + relu; float2 stores ----
    const int quad = lane >> 2;
    const int qt   = (lane & 3) << 1;
    #pragma unroll
    for (int mt = 0; mt < 4; ++mt) {
        const int m = d0 + wm * 64 + mt * 16 + quad;
        const float bv0 = bias[m];
        const float bv1 = bias[m + 8];
        float* r0 = out + ((size_t)b * DOUT + m) * TOUT;
        float* r1 = r0 + 8 * TOUT;
        #pragma unroll
        for (int nt = 0; nt < 4; ++nt) {
            const int t = t0 + wn * 32 + nt * 8 + qt;
            if (t < TOUT) {
                float2 v0, v1;
                v0.x = fmaxf(acc[mt][nt][0] + bv0, 0.0f);
                v0.y = fmaxf(acc[mt][nt][1] + bv0, 0.0f);
                v1.x = fmaxf(acc[mt][nt][2] + bv1, 0.0f);
                v1.y = fmaxf(acc[mt][nt][3] + bv1, 0.0f);
                *(float2*)&r0[t] = v0;
                *(float2*)&r1[t] = v1;
            }
        }
    }
}

extern "C" void kernel_launch(void* const* d_in, const int* in_sizes, int n_in,
                              void* d_out, int out_size) {
    const float* x    = (const float*)d_in[0];   // [B, T, D_in]
    const float* w    = (const float*)d_in[1];   // [D_out, D_in, KW]
    const float* bias = (const float*)d_in[2];   // [D_out]
    float* out = (float*)d_out;                  // [B, D_out, T_out]

    cudaFuncSetAttribute(tdnn_mma, cudaFuncAttributeMaxDynamicSharedMemorySize,
                         SMEM_BYTES);

    split_inputs<<<XVEC_BLOCKS + W_BLOCKS, 256>>>(x, w);

    dim3 grid(DOUT / TILE_M, (TOUT + TILE_N - 1) / TILE_N, BATCH);  // (4,4,32)
    tdnn_mma<<<grid, 512, SMEM_BYTES>>>(bias, out);
}

// round 5
// speedup vs baseline: 9.0828x; 2.0882x over previous
#include <cuda_runtime.h>
#include <cuda_fp16.h>
#include <cstdint>

// TDNN as implicit GEMM, single-pass fp16 mma.sync (HMMA).
// Both W and x rounded to fp16; measured x-only rounding error was 2.08e-4,
// adding W rounding ~sqrt(2)x -> ~2.9e-4 << 1e-3 threshold.
//   out[b,n,t] = relu(bias[n] + sum_{kappa<2560} W2[n][kappa] * x[b, t*512+kappa])
// W2[n][k*512+i] = w[n][i][k]; the x window per (b,t) is contiguous memory.

#define DIN   512
#define DOUT  512
#define TIN   1024
#define TOUT  1020
#define KW    5
#define KTOT  2560
#define BATCH 32

#define TILE_M 128        // Dout per CTA
#define TILE_N 128        // t per CTA
#define KC     64         // fp16 K per stage (128B rows, SW128)
#define NSTAGE (KTOT / KC)

#define XVEC_BLOCKS  ((BATCH * TIN * DIN) / 4 / 256)  // 16384
#define W_BLOCKS     ((DOUT * KTOT + 255) / 256)      // 5120

// ---------------- scratch (no allocation allowed) ----------------
__device__ __half g_xh[(size_t)BATCH * TIN * DIN];
__device__ __half g_wh[DOUT * KTOT];   // [n][k*512+i]

__global__ void split_inputs(const float* __restrict__ x,
                             const float* __restrict__ w) {
    int bid = blockIdx.x;
    if (bid < XVEC_BLOCKS) {
        int i4 = (bid * 256 + threadIdx.x) * 4;
        float4 v = *(const float4*)(x + i4);
        __half2 h0 = __floats2half2_rn(v.x, v.y);
        __half2 h1 = __floats2half2_rn(v.z, v.w);
        uint2 pk;
        pk.x = *(uint32_t*)&h0;
        pk.y = *(uint32_t*)&h1;
        *(uint2*)(g_xh + i4) = pk;
    } else {
        int idx = (bid - XVEC_BLOCKS) * 256 + threadIdx.x;
        if (idx >= DOUT * KTOT) return;
        int n   = idx / KTOT;
        int rem = idx - n * KTOT;
        int k   = rem >> 9;
        int i   = rem & 511;
        g_wh[idx] = __float2half_rn(w[(n * DIN + i) * KW + k]);
    }
}

// ---------------- PTX helpers (portable) ----------------
__device__ __forceinline__ uint32_t smem_u32(const void* p) {
    uint32_t a;
    asm("{ .reg .u64 t; cvta.to.shared.u64 t, %1; cvt.u32.u64 %0, t; }"
        : "=r"(a) : "l"(p));
    return a;
}
__device__ __forceinline__ void cpa16(uint32_t dst, const void* src) {
    asm volatile("cp.async.cg.shared.global [%0], [%1], 16;"
                 :: "r"(dst), "l"(__cvta_generic_to_global(src)) : "memory");
}
__device__ __forceinline__ void ldsm4(uint32_t* r, uint32_t a) {
    asm volatile("ldmatrix.sync.aligned.m8n8.x4.shared.b16 {%0,%1,%2,%3}, [%4];"
                 : "=r"(r[0]), "=r"(r[1]), "=r"(r[2]), "=r"(r[3]) : "r"(a));
}
__device__ __forceinline__ void mma16816(float* c, const uint32_t* a,
                                         const uint32_t* b) {
    asm volatile(
        "mma.sync.aligned.m16n8k16.row.col.f32.f16.f16.f32 "
        "{%0,%1,%2,%3}, {%4,%5,%6,%7}, {%8,%9}, {%0,%1,%2,%3};"
        : "+f"(c[0]), "+f"(c[1]), "+f"(c[2]), "+f"(c[3])
        : "r"(a[0]), "r"(a[1]), "r"(a[2]), "r"(a[3]), "r"(b[0]), "r"(b[1]));
}

// SMEM stage: A +0 (16KB)  B +16384 (16KB) -> 32KB/stage, 3 stages = 96KB
#define A_OFF 0u
#define B_OFF 16384u
#define STAGE_BYTES 32768u
#define NBUF 3
#define SMEM_BYTES (1024 + NBUF * 32768)

extern __shared__ char dyn_smem[];

__global__ __launch_bounds__(256, 2)
void tdnn_mma(const float* __restrict__ bias, float* __restrict__ out) {
    const int tid  = threadIdx.x;
    const int wid  = tid >> 5;
    const int lane = tid & 31;
    const int d0 = blockIdx.x * TILE_M;   // Dout tile base
    const int t0 = blockIdx.y * TILE_N;   // time tile base
    const int b  = blockIdx.z;

    const int wm = wid & 1;   // 2 warps along M (64 rows each)
    const int wn = wid >> 1;  // 4 warps along N (32 cols each)

    const uint32_t sb = (smem_u32(dyn_smem) + 1023u) & ~1023u;

    // ---- per-lane ldmatrix address precompute (SW128: 128B rows) ----
    const int grp  = lane >> 3;
    const int apar = grp >> 1;           // A: k-chunk parity
    uint32_t a_off[4]; int a_sw[4];
    #pragma unroll
    for (int mt = 0; mt < 4; ++mt) {
        int r = wm * 64 + mt * 16 + ((grp & 1) << 3) + (lane & 7);
        a_off[mt] = (uint32_t)(r << 7);
        a_sw[mt]  = r & 7;
    }
    const int bpar  = grp & 1;           // B: k-chunk parity
    const int ntoff = grp >> 1;
    uint32_t b_off[2]; int b_sw[2];
    #pragma unroll
    for (int np = 0; np < 2; ++np) {
        int r = wn * 32 + np * 16 + ntoff * 8 + (lane & 7);
        b_off[np] = (uint32_t)(r << 7);
        b_sw[np]  = r & 7;
    }

    float acc[4][4][4];
    #pragma unroll
    for (int mt = 0; mt < 4; ++mt)
        #pragma unroll
        for (int nt = 0; nt < 4; ++nt)
            #pragma unroll
            for (int q = 0; q < 4; ++q) acc[mt][nt][q] = 0.0f;

    // ---- stage loader: 256 threads, A 1024 + B 1024 cp.async chunks ----
    auto load_stage = [&](int s, uint32_t base) {
        const int kc = s * KC;
        #pragma unroll 4
        for (int c = tid; c < 1024; c += 256) {      // A: 128 rows x 8 chunks
            int row = c >> 3, ch = c & 7;
            uint32_t off = (uint32_t)((row << 7) | ((ch ^ (row & 7)) << 4));
            size_t gi = (size_t)(d0 + row) * KTOT + kc + ch * 8;
            cpa16(base + A_OFF + off, g_wh + gi);
        }
        #pragma unroll 4
        for (int c = tid; c < 1024; c += 256) {      // B: 128 rows x 8 chunks
            int row = c >> 3, ch = c & 7;
            int t = t0 + row;
            if (t > TIN - KW) t = TIN - KW;          // clamp; outputs masked
            uint32_t off = (uint32_t)((row << 7) | ((ch ^ (row & 7)) << 4));
            size_t gi = (size_t)b * (TIN * DIN) + (size_t)t * DIN + kc + ch * 8;
            cpa16(base + B_OFF + off, g_xh + gi);
        }
        asm volatile("cp.async.commit_group;" ::: "memory");
    };

    load_stage(0, sb);
    load_stage(1, sb + STAGE_BYTES);
    load_stage(2, sb + 2 * STAGE_BYTES);

    int cbuf = 0, lbuf = 0;
    for (int s = 0; s < NSTAGE; ++s) {
        if (s <= NSTAGE - 3)      asm volatile("cp.async.wait_group 2;" ::: "memory");
        else if (s == NSTAGE - 2) asm volatile("cp.async.wait_group 1;" ::: "memory");
        else                      asm volatile("cp.async.wait_group 0;" ::: "memory");
        __syncthreads();

        const uint32_t base = sb + (uint32_t)cbuf * STAGE_BYTES;
        #pragma unroll
        for (int kk = 0; kk < 4; ++kk) {
            uint32_t af[4][4], bf[8];
            #pragma unroll
            for (int mt = 0; mt < 4; ++mt) {
                uint32_t co = (uint32_t)((((kk << 1) + apar) ^ a_sw[mt]) << 4);
                ldsm4(af[mt], base + A_OFF + a_off[mt] + co);
            }
            #pragma unroll
            for (int np = 0; np < 2; ++np) {
                uint32_t co = (uint32_t)((((kk << 1) + bpar) ^ b_sw[np]) << 4);
                ldsm4(&bf[np * 4], base + B_OFF + b_off[np] + co);
            }
            #pragma unroll
            for (int mt = 0; mt < 4; ++mt)
                #pragma unroll
                for (int nt = 0; nt < 4; ++nt)
                    mma16816(acc[mt][nt], af[mt], &bf[nt * 2]);
        }
        __syncthreads();
        if (s + 3 < NSTAGE) load_stage(s + 3, sb + (uint32_t)lbuf * STAGE_BYTES);
        cbuf = (cbuf == NBUF - 1) ? 0 : cbuf + 1;
        lbuf = (lbuf == NBUF - 1) ? 0 : lbuf + 1;
    }

    // ---- epilogue: bias + relu; float2 stores ----
    const int quad = lane >> 2;
    const int qt   = (lane & 3) << 1;
    #pragma unroll
    for (int mt = 0; mt < 4; ++mt) {
        const int m = d0 + wm * 64 + mt * 16 + quad;
        const float bv0 = bias[m];
        const float bv1 = bias[m + 8];
        float* r0 = out + ((size_t)b * DOUT + m) * TOUT;
        float* r1 = r0 + 8 * TOUT;
        #pragma unroll
        for (int nt = 0; nt < 4; ++nt) {
            const int t = t0 + wn * 32 + nt * 8 + qt;
            if (t < TOUT) {
                float2 v0, v1;
                v0.x = fmaxf(acc[mt][nt][0] + bv0, 0.0f);
                v0.y = fmaxf(acc[mt][nt][1] + bv0, 0.0f);
                v1.x = fmaxf(acc[mt][nt][2] + bv1, 0.0f);
                v1.y = fmaxf(acc[mt][nt][3] + bv1, 0.0f);
                *(float2*)&r0[t] = v0;
                *(float2*)&r1[t] = v1;
            }
        }
    }
}

extern "C" void kernel_launch(void* const* d_in, const int* in_sizes, int n_in,
                              void* d_out, int out_size) {
    const float* x    = (const float*)d_in[0];   // [B, T, D_in]
    const float* w    = (const float*)d_in[1];   // [D_out, D_in, KW]
    const float* bias = (const float*)d_in[2];   // [D_out]
    float* out = (float*)d_out;                  // [B, D_out, T_out]

    cudaFuncSetAttribute(tdnn_mma, cudaFuncAttributeMaxDynamicSharedMemorySize,
                         SMEM_BYTES);

    split_inputs<<<XVEC_BLOCKS + W_BLOCKS, 256>>>(x, w);

    dim3 grid(DOUT / TILE_M, (TOUT + TILE_N - 1) / TILE_N, BATCH);  // (4,8,32)
    tdnn_mma<<<grid, 256, SMEM_BYTES>>>(bias, out);
}

// round 6
// speedup vs baseline: 9.3538x; 1.0298x over previous
#include <cuda_runtime.h>
#include <cuda_fp16.h>
#include <cstdint>

// TDNN as implicit GEMM, single-pass fp16 mma.sync (HMMA).
//   out[b,n,t] = relu(bias[n] + sum_{kappa<2560} W2[n][kappa] * x[b, t*512+kappa])
// W2[n][k*512+i] = w[n][i][k]; the x window per (b,t) is contiguous memory.
// Round 6: single __syncthreads per K-stage; load for stage s+2 issued
// immediately after the barrier (buffer (s+2)%3 == (s-1)%3, already drained).

#define DIN   512
#define DOUT  512
#define TIN   1024
#define TOUT  1020
#define KW    5
#define KTOT  2560
#define BATCH 32

#define TILE_M 128        // Dout per CTA
#define TILE_N 128        // t per CTA
#define KC     64         // fp16 K per stage (128B rows, SW128)
#define NSTAGE (KTOT / KC)

#define XVEC_BLOCKS  ((BATCH * TIN * DIN) / 8 / 256)  // 8 elems per thread
#define W_BLOCKS     ((DOUT * KTOT + 255) / 256)

// ---------------- scratch (no allocation allowed) ----------------
__device__ __half g_xh[(size_t)BATCH * TIN * DIN];
__device__ __half g_wh[DOUT * KTOT];   // [n][k*512+i]

__global__ void split_inputs(const float* __restrict__ x,
                             const float* __restrict__ w) {
    int bid = blockIdx.x;
    if (bid < XVEC_BLOCKS) {
        // 8 elems per thread as two independent float4s (MLP=2)
        int i8 = (bid * 256 + threadIdx.x) * 8;
        float4 v0 = *(const float4*)(x + i8);
        float4 v1 = *(const float4*)(x + i8 + 4);
        __half2 h0 = __floats2half2_rn(v0.x, v0.y);
        __half2 h1 = __floats2half2_rn(v0.z, v0.w);
        __half2 h2 = __floats2half2_rn(v1.x, v1.y);
        __half2 h3 = __floats2half2_rn(v1.z, v1.w);
        uint4 pk;
        pk.x = *(uint32_t*)&h0;
        pk.y = *(uint32_t*)&h1;
        pk.z = *(uint32_t*)&h2;
        pk.w = *(uint32_t*)&h3;
        *(uint4*)(g_xh + i8) = pk;
    } else {
        int idx = (bid - XVEC_BLOCKS) * 256 + threadIdx.x;
        if (idx >= DOUT * KTOT) return;
        int n   = idx / KTOT;
        int rem = idx - n * KTOT;
        int k   = rem >> 9;
        int i   = rem & 511;
        g_wh[idx] = __float2half_rn(w[(n * DIN + i) * KW + k]);
    }
}

// ---------------- PTX helpers (portable) ----------------
__device__ __forceinline__ uint32_t smem_u32(const void* p) {
    uint32_t a;
    asm("{ .reg .u64 t; cvta.to.shared.u64 t, %1; cvt.u32.u64 %0, t; }"
        : "=r"(a) : "l"(p));
    return a;
}
__device__ __forceinline__ void cpa16(uint32_t dst, const void* src) {
    asm volatile("cp.async.cg.shared.global [%0], [%1], 16;"
                 :: "r"(dst), "l"(__cvta_generic_to_global(src)) : "memory");
}
__device__ __forceinline__ void ldsm4(uint32_t* r, uint32_t a) {
    asm volatile("ldmatrix.sync.aligned.m8n8.x4.shared.b16 {%0,%1,%2,%3}, [%4];"
                 : "=r"(r[0]), "=r"(r[1]), "=r"(r[2]), "=r"(r[3]) : "r"(a));
}
__device__ __forceinline__ void mma16816(float* c, const uint32_t* a,
                                         const uint32_t* b) {
    asm volatile(
        "mma.sync.aligned.m16n8k16.row.col.f32.f16.f16.f32 "
        "{%0,%1,%2,%3}, {%4,%5,%6,%7}, {%8,%9}, {%0,%1,%2,%3};"
        : "+f"(c[0]), "+f"(c[1]), "+f"(c[2]), "+f"(c[3])
        : "r"(a[0]), "r"(a[1]), "r"(a[2]), "r"(a[3]), "r"(b[0]), "r"(b[1]));
}

// SMEM stage: A +0 (16KB)  B +16384 (16KB) -> 32KB/stage, 3 stages = 96KB
#define A_OFF 0u
#define B_OFF 16384u
#define STAGE_BYTES 32768u
#define NBUF 3
#define SMEM_BYTES (1024 + NBUF * 32768)

extern __shared__ char dyn_smem[];

__global__ __launch_bounds__(256, 2)
void tdnn_mma(const float* __restrict__ bias, float* __restrict__ out) {
    const int tid  = threadIdx.x;
    const int wid  = tid >> 5;
    const int lane = tid & 31;
    const int d0 = blockIdx.x * TILE_M;   // Dout tile base
    const int t0 = blockIdx.y * TILE_N;   // time tile base
    const int b  = blockIdx.z;

    const int wm = wid & 1;   // 2 warps along M (64 rows each)
    const int wn = wid >> 1;  // 4 warps along N (32 cols each)

    const uint32_t sb = (smem_u32(dyn_smem) + 1023u) & ~1023u;

    // row clamp for the last t-tile (outputs masked in epilogue)
    const int rmax = (TIN - KW) - t0;     // >= 127 except last tile

    // ---- per-lane ldmatrix address precompute (SW128: 128B rows) ----
    const int grp  = lane >> 3;
    const int apar = grp >> 1;           // A: k-chunk parity
    uint32_t a_off[4]; int a_sw[4];
    #pragma unroll
    for (int mt = 0; mt < 4; ++mt) {
        int r = wm * 64 + mt * 16 + ((grp & 1) << 3) + (lane & 7);
        a_off[mt] = (uint32_t)(r << 7);
        a_sw[mt]  = r & 7;
    }
    const int bpar  = grp & 1;           // B: k-chunk parity
    const int ntoff = grp >> 1;
    uint32_t b_off[2]; int b_sw[2];
    #pragma unroll
    for (int np = 0; np < 2; ++np) {
        int r = wn * 32 + np * 16 + ntoff * 8 + (lane & 7);
        b_off[np] = (uint32_t)(r << 7);
        b_sw[np]  = r & 7;
    }

    float acc[4][4][4];
    #pragma unroll
    for (int mt = 0; mt < 4; ++mt)
        #pragma unroll
        for (int nt = 0; nt < 4; ++nt)
            #pragma unroll
            for (int q = 0; q < 4; ++q) acc[mt][nt][q] = 0.0f;

    // ---- stage loader: 256 threads, A 1024 + B 1024 cp.async chunks ----
    auto load_stage = [&](int s, uint32_t base) {
        const int kc = s * KC;
        #pragma unroll 4
        for (int c = tid; c < 1024; c += 256) {      // A: 128 rows x 8 chunks
            int row = c >> 3, ch = c & 7;
            uint32_t off = (uint32_t)((row << 7) | ((ch ^ (row & 7)) << 4));
            size_t gi = (size_t)(d0 + row) * KTOT + kc + ch * 8;
            cpa16(base + A_OFF + off, g_wh + gi);
        }
        #pragma unroll 4
        for (int c = tid; c < 1024; c += 256) {      // B: 128 rows x 8 chunks
            int row = c >> 3, ch = c & 7;
            int t = t0 + min(row, rmax);             // clamp; outputs masked
            uint32_t off = (uint32_t)((row << 7) | ((ch ^ (row & 7)) << 4));
            size_t gi = (size_t)b * (TIN * DIN) + (size_t)t * DIN + kc + ch * 8;
            cpa16(base + B_OFF + off, g_xh + gi);
        }
        asm volatile("cp.async.commit_group;" ::: "memory");
    };

    load_stage(0, sb);
    load_stage(1, sb + STAGE_BYTES);

    uint32_t cbuf = 0, lbuf = 2;   // compute buf (s%3), load buf ((s+2)%3)
    for (int s = 0; s < NSTAGE; ++s) {
        if (s < NSTAGE - 1) asm volatile("cp.async.wait_group 1;" ::: "memory");
        else                asm volatile("cp.async.wait_group 0;" ::: "memory");
        __syncthreads();
        // Issue next load FIRST: buffer (s+2)%3 == (s-1)%3, whose compute all
        // warps finished before this barrier. Gives loads a 2-stage window.
        if (s + 2 < NSTAGE) load_stage(s + 2, sb + lbuf * STAGE_BYTES);

        const uint32_t base = sb + cbuf * STAGE_BYTES;
        #pragma unroll
        for (int kk = 0; kk < 4; ++kk) {
            uint32_t af[4][4], bf[8];
            #pragma unroll
            for (int mt = 0; mt < 4; ++mt) {
                uint32_t co = (uint32_t)((((kk << 1) + apar) ^ a_sw[mt]) << 4);
                ldsm4(af[mt], base + A_OFF + a_off[mt] + co);
            }
            #pragma unroll
            for (int np = 0; np < 2; ++np) {
                uint32_t co = (uint32_t)((((kk << 1) + bpar) ^ b_sw[np]) << 4);
                ldsm4(&bf[np * 4], base + B_OFF + b_off[np] + co);
            }
            #pragma unroll
            for (int mt = 0; mt < 4; ++mt)
                #pragma unroll
                for (int nt = 0; nt < 4; ++nt)
                    mma16816(acc[mt][nt], af[mt], &bf[nt * 2]);
        }
        cbuf = (cbuf == NBUF - 1) ? 0 : cbuf + 1;
        lbuf = (lbuf == NBUF - 1) ? 0 : lbuf + 1;
    }

    // ---- epilogue: bias + relu; float2 stores ----
    const int quad = lane >> 2;
    const int qt   = (lane & 3) << 1;
    #pragma unroll
    for (int mt = 0; mt < 4; ++mt) {
        const int m = d0 + wm * 64 + mt * 16 + quad;
        const float bv0 = bias[m];
        const float bv1 = bias[m + 8];
        float* r0 = out + ((size_t)b * DOUT + m) * TOUT;
        float* r1 = r0 + 8 * TOUT;
        #pragma unroll
        for (int nt = 0; nt < 4; ++nt) {
            const int t = t0 + wn * 32 + nt * 8 + qt;
            if (t < TOUT) {
                float2 v0, v1;
                v0.x = fmaxf(acc[mt][nt][0] + bv0, 0.0f);
                v0.y = fmaxf(acc[mt][nt][1] + bv0, 0.0f);
                v1.x = fmaxf(acc[mt][nt][2] + bv1, 0.0f);
                v1.y = fmaxf(acc[mt][nt][3] + bv1, 0.0f);
                *(float2*)&r0[t] = v0;
                *(float2*)&r1[t] = v1;
            }
        }
    }
}

extern "C" void kernel_launch(void* const* d_in, const int* in_sizes, int n_in,
                              void* d_out, int out_size) {
    const float* x    = (const float*)d_in[0];   // [B, T, D_in]
    const float* w    = (const float*)d_in[1];   // [D_out, D_in, KW]
    const float* bias = (const float*)d_in[2];   // [D_out]
    float* out = (float*)d_out;                  // [B, D_out, T_out]

    cudaFuncSetAttribute(tdnn_mma, cudaFuncAttributeMaxDynamicSharedMemorySize,
                         SMEM_BYTES);

    split_inputs<<<XVEC_BLOCKS + W_BLOCKS, 256>>>(x, w);

    dim3 grid(DOUT / TILE_M, (TOUT + TILE_N - 1) / TILE_N, BATCH);  // (4,8,32)
    tdnn_mma<<<grid, 256, SMEM_BYTES>>>(bias, out);
}

// round 7
// speedup vs baseline: 9.4302x; 1.0082x over previous
#include <cuda_runtime.h>
#include <cuda_fp16.h>
#include <cstdint>

// TDNN as implicit GEMM, single-pass fp16 mma.sync (HMMA).
//   out[b,n,t] = relu(bias[n] + sum_{kappa<2560} W2[n][kappa] * x[b, t*512+kappa])
// W2[n][k*512+i] = w[n][i][k]; the x window per (b,t) is contiguous memory.
// Round 7: register-neutral fragment double-buffering (A per-mt, B per-kk)
// to hide LDSM latency behind MMA groups; coalesced w-split.

#define DIN   512
#define DOUT  512
#define TIN   1024
#define TOUT  1020
#define KW    5
#define KTOT  2560
#define BATCH 32

#define TILE_M 128
#define TILE_N 128
#define KC     64
#define NSTAGE (KTOT / KC)

#define XVEC_BLOCKS ((BATCH * TIN * DIN) / 8 / 256)   // 8192
#define WPAIR_BLOCKS ((DOUT * DIN) / 256)             // 1024 (one thread per (n,i))

// ---------------- scratch (no allocation allowed) ----------------
__device__ __half g_xh[(size_t)BATCH * TIN * DIN];
__device__ __half g_wh[DOUT * KTOT];   // [n][k*512+i]

__global__ void split_inputs(const float* __restrict__ x,
                             const float* __restrict__ w) {
    int bid = blockIdx.x;
    if (bid < XVEC_BLOCKS) {
        int i8 = (bid * 256 + threadIdx.x) * 8;
        float4 v0 = *(const float4*)(x + i8);
        float4 v1 = *(const float4*)(x + i8 + 4);
        __half2 h0 = __floats2half2_rn(v0.x, v0.y);
        __half2 h1 = __floats2half2_rn(v0.z, v0.w);
        __half2 h2 = __floats2half2_rn(v1.x, v1.y);
        __half2 h3 = __floats2half2_rn(v1.z, v1.w);
        uint4 pk;
        pk.x = *(uint32_t*)&h0;
        pk.y = *(uint32_t*)&h1;
        pk.z = *(uint32_t*)&h2;
        pk.w = *(uint32_t*)&h3;
        *(uint4*)(g_xh + i8) = pk;
    } else {
        // one thread per (n,i): 5 contiguous fp32 reads, 5 coalesced fp16 writes
        int p = (bid - XVEC_BLOCKS) * 256 + threadIdx.x;   // p = n*512 + i
        int n = p >> 9;
        int i = p & 511;
        const float* wp = w + (size_t)p * KW;
        #pragma unroll
        for (int k = 0; k < KW; ++k)
            g_wh[n * KTOT + k * DIN + i] = __float2half_rn(wp[k]);
    }
}

// ---------------- PTX helpers (portable) ----------------
__device__ __forceinline__ uint32_t smem_u32(const void* p) {
    uint32_t a;
    asm("{ .reg .u64 t; cvta.to.shared.u64 t, %1; cvt.u32.u64 %0, t; }"
        : "=r"(a) : "l"(p));
    return a;
}
__device__ __forceinline__ void cpa16(uint32_t dst, const void* src) {
    asm volatile("cp.async.cg.shared.global [%0], [%1], 16;"
                 :: "r"(dst), "l"(__cvta_generic_to_global(src)) : "memory");
}
__device__ __forceinline__ void ldsm4(uint32_t* r, uint32_t a) {
    asm volatile("ldmatrix.sync.aligned.m8n8.x4.shared.b16 {%0,%1,%2,%3}, [%4];"
                 : "=r"(r[0]), "=r"(r[1]), "=r"(r[2]), "=r"(r[3]) : "r"(a));
}
__device__ __forceinline__ void mma16816(float* c, const uint32_t* a,
                                         const uint32_t* b) {
    asm volatile(
        "mma.sync.aligned.m16n8k16.row.col.f32.f16.f16.f32 "
        "{%0,%1,%2,%3}, {%4,%5,%6,%7}, {%8,%9}, {%0,%1,%2,%3};"
        : "+f"(c[0]), "+f"(c[1]), "+f"(c[2]), "+f"(c[3])
        : "r"(a[0]), "r"(a[1]), "r"(a[2]), "r"(a[3]), "r"(b[0]), "r"(b[1]));
}

#define A_OFF 0u
#define B_OFF 16384u
#define STAGE_BYTES 32768u
#define NBUF 3
#define SMEM_BYTES (1024 + NBUF * 32768)

extern __shared__ char dyn_smem[];

__global__ __launch_bounds__(256, 2)
void tdnn_mma(const float* __restrict__ bias, float* __restrict__ out) {
    const int tid  = threadIdx.x;
    const int wid  = tid >> 5;
    const int lane = tid & 31;
    const int d0 = blockIdx.x * TILE_M;
    const int t0 = blockIdx.y * TILE_N;
    const int b  = blockIdx.z;

    const int wm = wid & 1;   // 2 warps along M (64 rows each)
    const int wn = wid >> 1;  // 4 warps along N (32 cols each)

    const uint32_t sb = (smem_u32(dyn_smem) + 1023u) & ~1023u;
    const int rmax = (TIN - KW) - t0;

    // ---- per-lane ldmatrix address precompute (SW128: 128B rows) ----
    const int grp  = lane >> 3;
    const int apar = grp >> 1;
    uint32_t a_off[4]; int a_sw[4];
    #pragma unroll
    for (int mt = 0; mt < 4; ++mt) {
        int r = wm * 64 + mt * 16 + ((grp & 1) << 3) + (lane & 7);
        a_off[mt] = (uint32_t)(r << 7);
        a_sw[mt]  = r & 7;
    }
    const int bpar  = grp & 1;
    const int ntoff = grp >> 1;
    uint32_t b_off[2]; int b_sw[2];
    #pragma unroll
    for (int np = 0; np < 2; ++np) {
        int r = wn * 32 + np * 16 + ntoff * 8 + (lane & 7);
        b_off[np] = (uint32_t)(r << 7);
        b_sw[np]  = r & 7;
    }

    float acc[4][4][4];
    #pragma unroll
    for (int mt = 0; mt < 4; ++mt)
        #pragma unroll
        for (int nt = 0; nt < 4; ++nt)
            #pragma unroll
            for (int q = 0; q < 4; ++q) acc[mt][nt][q] = 0.0f;

    auto load_stage = [&](int s, uint32_t base) {
        const int kc = s * KC;
        #pragma unroll 4
        for (int c = tid; c < 1024; c += 256) {      // A
            int row = c >> 3, ch = c & 7;
            uint32_t off = (uint32_t)((row << 7) | ((ch ^ (row & 7)) << 4));
            size_t gi = (size_t)(d0 + row) * KTOT + kc + ch * 8;
            cpa16(base + A_OFF + off, g_wh + gi);
        }
        #pragma unroll 4
        for (int c = tid; c < 1024; c += 256) {      // B
            int row = c >> 3, ch = c & 7;
            int t = t0 + min(row, rmax);
            uint32_t off = (uint32_t)((row << 7) | ((ch ^ (row & 7)) << 4));
            size_t gi = (size_t)b * (TIN * DIN) + (size_t)t * DIN + kc + ch * 8;
            cpa16(base + B_OFF + off, g_xh + gi);
        }
        asm volatile("cp.async.commit_group;" ::: "memory");
    };

    load_stage(0, sb);
    load_stage(1, sb + STAGE_BYTES);

    uint32_t cbuf = 0, lbuf = 2;
    for (int s = 0; s < NSTAGE; ++s) {
        if (s < NSTAGE - 1) asm volatile("cp.async.wait_group 1;" ::: "memory");
        else                asm volatile("cp.async.wait_group 0;" ::: "memory");
        __syncthreads();
        if (s + 2 < NSTAGE) load_stage(s + 2, sb + lbuf * STAGE_BYTES);

        const uint32_t base = sb + cbuf * STAGE_BYTES;
        uint32_t af[2][4], bf[2][8];

        // prefetch B fragments for kk=0
        #pragma unroll
        for (int np = 0; np < 2; ++np) {
            uint32_t co = (uint32_t)((bpar ^ b_sw[np]) << 4);
            ldsm4(&bf[0][np * 4], base + B_OFF + b_off[np] + co);
        }
        #pragma unroll
        for (int kk = 0; kk < 4; ++kk) {
            // prefetch A for mt=0 of this kk
            {
                uint32_t co = (uint32_t)((((kk << 1) + apar) ^ a_sw[0]) << 4);
                ldsm4(af[0], base + A_OFF + a_off[0] + co);
            }
            // prefetch B fragments for kk+1 (consumed one full mt-loop later)
            if (kk < 3) {
                #pragma unroll
                for (int np = 0; np < 2; ++np) {
                    uint32_t co =
                        (uint32_t)(((((kk + 1) << 1) + bpar) ^ b_sw[np]) << 4);
                    ldsm4(&bf[(kk + 1) & 1][np * 4],
                          base + B_OFF + b_off[np] + co);
                }
            }
            #pragma unroll
            for (int mt = 0; mt < 4; ++mt) {
                if (mt < 3) {   // prefetch A for mt+1 while computing mt
                    uint32_t co =
                        (uint32_t)((((kk << 1) + apar) ^ a_sw[mt + 1]) << 4);
                    ldsm4(af[(mt + 1) & 1], base + A_OFF + a_off[mt + 1] + co);
                }
                #pragma unroll
                for (int nt = 0; nt < 4; ++nt)
                    mma16816(acc[mt][nt], af[mt & 1], &bf[kk & 1][nt * 2]);
            }
        }
        cbuf = (cbuf == NBUF - 1) ? 0 : cbuf + 1;
        lbuf = (lbuf == NBUF - 1) ? 0 : lbuf + 1;
    }

    // ---- epilogue: bias + relu; float2 stores ----
    const int quad = lane >> 2;
    const int qt   = (lane & 3) << 1;
    #pragma unroll
    for (int mt = 0; mt < 4; ++mt) {
        const int m = d0 + wm * 64 + mt * 16 + quad;
        const float bv0 = bias[m];
        const float bv1 = bias[m + 8];
        float* r0 = out + ((size_t)b * DOUT + m) * TOUT;
        float* r1 = r0 + 8 * TOUT;
        #pragma unroll
        for (int nt = 0; nt < 4; ++nt) {
            const int t = t0 + wn * 32 + nt * 8 + qt;
            if (t < TOUT) {
                float2 v0, v1;
                v0.x = fmaxf(acc[mt][nt][0] + bv0, 0.0f);
                v0.y = fmaxf(acc[mt][nt][1] + bv0, 0.0f);
                v1.x = fmaxf(acc[mt][nt][2] + bv1, 0.0f);
                v1.y = fmaxf(acc[mt][nt][3] + bv1, 0.0f);
                *(float2*)&r0[t] = v0;
                *(float2*)&r1[t] = v1;
            }
        }
    }
}

extern "C" void kernel_launch(void* const* d_in, const int* in_sizes, int n_in,
                              void* d_out, int out_size) {
    const float* x    = (const float*)d_in[0];
    const float* w    = (const float*)d_in[1];
    const float* bias = (const float*)d_in[2];
    float* out = (float*)d_out;

    cudaFuncSetAttribute(tdnn_mma, cudaFuncAttributeMaxDynamicSharedMemorySize,
                         SMEM_BYTES);

    split_inputs<<<XVEC_BLOCKS + WPAIR_BLOCKS, 256>>>(x, w);

    dim3 grid(DOUT / TILE_M, (TOUT + TILE_N - 1) / TILE_N, BATCH);
    tdnn_mma<<<grid, 256, SMEM_BYTES>>>(bias, out);
}